// round 10
// baseline (speedup 1.0000x reference)
#include <cuda_runtime.h>

// Problem constants (fixed by the reference: B=8, N=4096, D=2)
#define BQ       8
#define NPTS     4096
#define NSETS    16                  // 8 batches x {y_true, y_pred}
#define NBINS    512
#define XMAX     5.0f
#define BSCALE   (NBINS / (2.0f * XMAX))
#define ATHREADS 1024
#define BTHREADS 512
#define NB_B     128                 // search blocks: 8 tiles x 8 batches x 2 dirs
#define NPART    (NB_B + NSETS)      // 144 partials

// Scratch (device globals — allocation-free per harness rules)
__device__ float2 g_pts[NSETS][NPTS + 8];        // sorted by x + sentinels
__device__ int    g_binStart[NSETS][NBINS + 1];  // first idx with bin(px) >= b
__device__ float  g_partials[NPART];
__device__ int    g_counter = 0;                 // reset by last search block

__device__ __forceinline__ int binOf(float x) {
    int b = (int)((x + XMAX) * BSCALE);
    return min(max(b, 0), NBINS - 1);
}

// ───────────────────────── Kernel A: EMD + sort + bin index ─────────────────
// Block s handles set s: t = s&1 (0 = y_true, 1 = y_pred), batch = s>>1.
__global__ __launch_bounds__(ATHREADS, 1)
void prep_kernel(const float* __restrict__ yt, const float* __restrict__ yp) {
    __shared__ float2 sh[NPTS];      // 32 KB sort buffer
    __shared__ float  red[ATHREADS]; //  4 KB

    const int tid = threadIdx.x;
    const int s   = blockIdx.x;
    const int t   = s & 1;
    const int b   = s >> 1;
    const float2* src = reinterpret_cast<const float2*>((t ? yp : yt)) + (size_t)b * NPTS;

    // EMD partial (computed from raw arrays, index-aligned pairs): t==0 blocks only.
    float e = 0.0f;
    if (t == 0) {
        const float2* T = reinterpret_cast<const float2*>(yt) + (size_t)b * NPTS;
        const float2* P = reinterpret_cast<const float2*>(yp) + (size_t)b * NPTS;
        for (int i = tid; i < NPTS; i += ATHREADS) {
            const float2 tv = T[i], pv = P[i];
            const float d0 = tv.x - pv.x;
            const float d1 = (tv.x + tv.y) - (pv.x + pv.y);
            e = fmaf(d0, d0, e);
            e = fmaf(d1, d1, e);
        }
    }
    red[tid] = e;
    __syncthreads();
    for (int w = ATHREADS / 2; w > 0; w >>= 1) {
        if (tid < w) red[tid] += red[tid + w];
        __syncthreads();
    }
    if (tid == 0)
        g_partials[NB_B + s] = red[0] * (1.0f / ((float)BQ * NPTS * 2));

    // Load points into shared.
    for (int i = tid; i < NPTS; i += ATHREADS) sh[i] = src[i];
    __syncthreads();

    // Bitonic sort by x (deterministic network, 78 passes).
    for (int k = 2; k <= NPTS; k <<= 1) {
        for (int jj = k >> 1; jj > 0; jj >>= 1) {
            for (int i = tid; i < NPTS; i += ATHREADS) {
                const int ixj = i ^ jj;
                if (ixj > i) {
                    const bool up = ((i & k) == 0);
                    const float2 a = sh[i];
                    const float2 c = sh[ixj];
                    if ((a.x > c.x) == up) { sh[i] = c; sh[ixj] = a; }
                }
            }
            __syncthreads();
        }
    }

    // Write sorted points + sentinels.
    for (int i = tid; i < NPTS; i += ATHREADS) g_pts[s][i] = sh[i];
    if (tid < 8) g_pts[s][NPTS + tid] = make_float2(1e30f, 0.0f);

    // Bin start index: binStart[b] = first i with bin(sh[i].x) >= b.
    for (int i = tid; i < NPTS; i += ATHREADS) {
        const int b1 = binOf(sh[i].x);
        const int b0 = (i == 0) ? -1 : binOf(sh[i - 1].x);
        for (int bb = b0 + 1; bb <= b1; bb++) g_binStart[s][bb] = i;
    }
    if (tid == 0) {
        const int bl = binOf(sh[NPTS - 1].x);
        for (int bb = bl + 1; bb <= NBINS; bb++) g_binStart[s][bb] = NPTS;
    }
}

// ───────────────────────── Kernel B: pruned NN search ───────────────────────
// Grid (8 tiles, 8 batches, 2 dirs); 1 query per thread, queries in sorted order.
__global__ __launch_bounds__(BTHREADS, 1)
void search_kernel(float* __restrict__ out) {
    __shared__ float red[BTHREADS];
    __shared__ bool  isLast;

    const int tid  = threadIdx.x;
    const int dir  = blockIdx.z;
    const int b    = blockIdx.y;
    const int sq   = (b << 1) | dir;        // query set (dir0: y_true)
    const int sr   = (b << 1) | (1 - dir);  // reference set
    const int p    = blockIdx.x * BTHREADS + tid;

    const float2 q = g_pts[sq][p];
    const float2* __restrict__ R = g_pts[sr];
    const int j0 = g_binStart[sr][binOf(q.x)];   // first ref with px >= home-bin left edge

    float best = 1e30f;

    // Right scan (px non-decreasing): chunk of 4 speculative loads; break check on
    // the farthest element only (overshoot evaluates valid candidates — harmless).
    int j = j0;
    while (j < NPTS) {
        const float2 p0 = R[j], p1 = R[j + 1], p2 = R[j + 2], p3 = R[j + 3];
        float dx, dy;
        dx = p0.x - q.x; dy = p0.y - q.y; best = fminf(best, fmaf(dx, dx, dy * dy));
        dx = p1.x - q.x; dy = p1.y - q.y; best = fminf(best, fmaf(dx, dx, dy * dy));
        dx = p2.x - q.x; dy = p2.y - q.y; best = fminf(best, fmaf(dx, dx, dy * dy));
        const float dx3 = p3.x - q.x;
        dy = p3.y - q.y; best = fminf(best, fmaf(dx3, dx3, dy * dy));
        if (dx3 > 0.0f && dx3 * dx3 >= best) break;
        j += 4;
    }

    // Left scan (all px < qx here, dx = qx - px non-decreasing as j falls).
    j = j0 - 1;
    while (j >= 0) {
        const int i1 = max(j - 1, 0), i2 = max(j - 2, 0), i3 = max(j - 3, 0);
        const float2 p0 = R[j], p1 = R[i1], p2 = R[i2], p3 = R[i3];
        float dx, dy;
        dx = q.x - p0.x; dy = q.y - p0.y; best = fminf(best, fmaf(dx, dx, dy * dy));
        dx = q.x - p1.x; dy = q.y - p1.y; best = fminf(best, fmaf(dx, dx, dy * dy));
        dx = q.x - p2.x; dy = q.y - p2.y; best = fminf(best, fmaf(dx, dx, dy * dy));
        const float dx3 = q.x - p3.x;
        dy = q.y - p3.y; best = fminf(best, fmaf(dx3, dx3, dy * dy));
        if (dx3 * dx3 >= best) break;
        j -= 4;
    }

    // Chamfer contribution: d2 >= 0 by construction (matches reference clamp).
    float local = best * (1.0f / BQ);

    // Deterministic block tree reduction.
    red[tid] = local;
    __syncthreads();
    for (int w = BTHREADS / 2; w > 0; w >>= 1) {
        if (tid < w) red[tid] += red[tid + w];
        __syncthreads();
    }
    const int bid = (blockIdx.z * gridDim.y + blockIdx.y) * gridDim.x + blockIdx.x;
    if (tid == 0) {
        g_partials[bid] = red[0];
        __threadfence();
        const int c = atomicAdd(&g_counter, 1);
        isLast = (c == NB_B - 1);
    }
    __syncthreads();

    // Last block: deterministic fixed-order sum of all 144 partials.
    if (isLast) {
        float v = 0.0f;
        if (tid < NPART) {
            __threadfence();
            v = *((volatile float*)&g_partials[tid]);
        }
        red[tid] = v;
        __syncthreads();
        for (int w = BTHREADS / 2; w > 0; w >>= 1) {
            if (tid < w) red[tid] += red[tid + w];
            __syncthreads();
        }
        if (tid == 0) {
            out[0] = red[0];
            g_counter = 0;   // reset for next graph replay
        }
    }
}

extern "C" void kernel_launch(void* const* d_in, const int* in_sizes, int n_in,
                              void* d_out, int out_size) {
    const float* y_true = (const float*)d_in[0];
    const float* y_pred = (const float*)d_in[1];
    float* out = (float*)d_out;

    prep_kernel<<<NSETS, ATHREADS>>>(y_true, y_pred);
    dim3 grid(NPTS / BTHREADS / 1, BQ, 2);   // (8, 8, 2)
    search_kernel<<<grid, BTHREADS>>>(out);
}

// round 11
// speedup vs baseline: 2.4611x; 2.4611x over previous
#include <cuda_runtime.h>

// Problem constants (fixed by the reference: B=8, N=4096, D=2)
#define BQ       8
#define NPTS     4096
#define NSETS    16                  // 8 batches x {y_true, y_pred}
#define NBINS    512
#define XMAX     5.0f
#define BINW     (2.0f * XMAX / NBINS)
#define BSCALE   (NBINS / (2.0f * XMAX))
#define PTHREADS 512
#define STHREADS 512
#define NB_B     128                 // search blocks: 8 tiles x 8 batches x 2 dirs
#define NPART    (NB_B + NSETS)      // 144 partials

// Scratch (device globals — allocation-free per harness rules)
__device__ float2 g_pts[NSETS][NPTS];            // bin-ordered points
__device__ int    g_binStart[NSETS][NBINS + 1];  // bin b occupies [start[b], start[b+1])
__device__ float  g_partials[NPART];
__device__ int    g_counter = 0;                 // reset by last search block

__device__ __forceinline__ int binOf(float x) {
    int b = (int)((x + XMAX) * BSCALE);
    return min(max(b, 0), NBINS - 1);
}
__device__ __forceinline__ float binEdge(int b) {   // left edge of bin b
    return -XMAX + (float)b * BINW;
}

// ─────────────── Kernel A: EMD partial + counting sort by x-bin ──────────────
// Block s handles set s: t = s&1 (0 = y_true, 1 = y_pred), batch = s>>1.
__global__ __launch_bounds__(PTHREADS, 1)
void prep_kernel(const float* __restrict__ yt, const float* __restrict__ yp) {
    __shared__ int   hist[NBINS];       // histogram, then scatter cursors
    __shared__ int   scn[NBINS];        // inclusive-scan workspace
    __shared__ int   start[NBINS + 1];  // exclusive prefix
    __shared__ float red[PTHREADS];

    const int tid = threadIdx.x;
    const int s   = blockIdx.x;
    const int t   = s & 1;
    const int b   = s >> 1;
    const float2* src = reinterpret_cast<const float2*>((t ? yp : yt)) + (size_t)b * NPTS;

    // EMD partial (index-aligned pairs); computed once per batch (t==0 blocks).
    float e = 0.0f;
    if (t == 0) {
        const float2* T = reinterpret_cast<const float2*>(yt) + (size_t)b * NPTS;
        const float2* P = reinterpret_cast<const float2*>(yp) + (size_t)b * NPTS;
        for (int i = tid; i < NPTS; i += PTHREADS) {
            const float2 tv = T[i], pv = P[i];
            const float d0 = tv.x - pv.x;
            const float d1 = (tv.x + tv.y) - (pv.x + pv.y);
            e = fmaf(d0, d0, e);
            e = fmaf(d1, d1, e);
        }
    }
    red[tid] = e;
    __syncthreads();
    for (int w = PTHREADS / 2; w > 0; w >>= 1) {
        if (tid < w) red[tid] += red[tid + w];
        __syncthreads();
    }
    if (tid == 0)
        g_partials[NB_B + s] = red[0] * (1.0f / ((float)BQ * NPTS * 2));

    // ── Counting sort by bin ──
    if (tid < NBINS) hist[tid] = 0;
    __syncthreads();
    for (int i = tid; i < NPTS; i += PTHREADS)
        atomicAdd(&hist[binOf(src[i].x)], 1);
    __syncthreads();

    // Inclusive scan over 512 bins (Hillis–Steele, 512 active threads).
    if (tid < NBINS) scn[tid] = hist[tid];
    __syncthreads();
    for (int off = 1; off < NBINS; off <<= 1) {
        int v = 0;
        if (tid < NBINS && tid >= off) v = scn[tid - off];
        __syncthreads();
        if (tid < NBINS) scn[tid] += v;
        __syncthreads();
    }
    if (tid == 0) start[0] = 0;
    if (tid < NBINS) start[tid + 1] = scn[tid];
    // reset cursors for scatter
    if (tid < NBINS) hist[tid] = 0;
    __syncthreads();

    // Scatter (within-bin order atomic-dependent — harmless: consumers take
    // an order-invariant min over each bin's SET, so output is deterministic).
    for (int i = tid; i < NPTS; i += PTHREADS) {
        const float2 p = src[i];
        const int bb = binOf(p.x);
        const int pos = start[bb] + atomicAdd(&hist[bb], 1);
        g_pts[s][pos] = p;
    }
    for (int i = tid; i <= NBINS; i += PTHREADS)
        g_binStart[s][i] = start[i];
}

// ─────────────── Kernel B: exact NN via bin expansion in SHARED ──────────────
// Grid (8 tiles, 8 batches, 2 dirs); 1 query/thread in ORIGINAL index order.
__global__ __launch_bounds__(STHREADS, 1)
void search_kernel(const float* __restrict__ yt, const float* __restrict__ yp,
                   float* __restrict__ out) {
    __shared__ float2 shPts[NPTS];        // 32 KB: full bin-ordered ref set
    __shared__ int    shStart[NBINS + 1]; //  2 KB
    __shared__ float  red[STHREADS];      //  2 KB
    __shared__ bool   isLast;

    const int tid = threadIdx.x;
    const int dir = blockIdx.z;
    const int b   = blockIdx.y;
    const int sr  = (b << 1) | (1 - dir);    // reference set id
    const float* qsrc = (dir == 0 ? yt : yp) + (size_t)b * NPTS * 2;

    // Stage the full reference set + bin index into shared (coalesced).
    for (int i = tid; i < NPTS; i += STHREADS) shPts[i] = g_pts[sr][i];
    for (int i = tid; i <= NBINS; i += STHREADS) shStart[i] = g_binStart[sr][i];
    __syncthreads();

    // Query (original order -> coalesced load, deterministic reduction order).
    const int p = blockIdx.x * STHREADS + tid;
    const float2 q = reinterpret_cast<const float2*>(qsrc)[p];
    const int qb = binOf(q.x);

    float best = 1e30f;
    // Home bin.
    for (int j = shStart[qb]; j < shStart[qb + 1]; j++) {
        const float2 r = shPts[j];
        const float dx = r.x - q.x, dy = r.y - q.y;
        best = fminf(best, fmaf(dx, dx, dy * dy));
    }
    // Expand toward the nearer unscanned side until gap^2 >= best (exact:
    // every unscanned point has |dx| >= gap, so d2 >= gap^2).
    int lo = qb, hi = qb;
    for (;;) {
        const float lgap = (lo > 0)         ? (q.x - binEdge(lo))     : 1e30f;
        const float rgap = (hi < NBINS - 1) ? (binEdge(hi + 1) - q.x) : 1e30f;
        const float gap  = fminf(lgap, rgap);
        if (gap * gap >= best) break;
        int nb;
        if (lgap <= rgap) { lo--; nb = lo; } else { hi++; nb = hi; }
        for (int j = shStart[nb]; j < shStart[nb + 1]; j++) {
            const float2 r = shPts[j];
            const float dx = r.x - q.x, dy = r.y - q.y;
            best = fminf(best, fmaf(dx, dx, dy * dy));
        }
    }

    // Chamfer contribution: d2 >= 0 by construction (matches reference clamp).
    float local = best * (1.0f / BQ);

    // Deterministic block tree reduction (order fixed by original query index).
    red[tid] = local;
    __syncthreads();
    for (int w = STHREADS / 2; w > 0; w >>= 1) {
        if (tid < w) red[tid] += red[tid + w];
        __syncthreads();
    }
    const int bid = (blockIdx.z * gridDim.y + blockIdx.y) * gridDim.x + blockIdx.x;
    if (tid == 0) {
        g_partials[bid] = red[0];
        __threadfence();
        const int c = atomicAdd(&g_counter, 1);
        isLast = (c == NB_B - 1);
    }
    __syncthreads();

    // Last block: deterministic fixed-order sum of all 144 partials.
    if (isLast) {
        float v = 0.0f;
        if (tid < NPART) {
            __threadfence();
            v = *((volatile float*)&g_partials[tid]);
        }
        red[tid] = v;
        __syncthreads();
        for (int w = STHREADS / 2; w > 0; w >>= 1) {
            if (tid < w) red[tid] += red[tid + w];
            __syncthreads();
        }
        if (tid == 0) {
            out[0] = red[0];
            g_counter = 0;   // reset for next graph replay
        }
    }
}

extern "C" void kernel_launch(void* const* d_in, const int* in_sizes, int n_in,
                              void* d_out, int out_size) {
    const float* y_true = (const float*)d_in[0];
    const float* y_pred = (const float*)d_in[1];
    float* out = (float*)d_out;

    prep_kernel<<<NSETS, PTHREADS>>>(y_true, y_pred);
    dim3 grid(NPTS / STHREADS, BQ, 2);   // (8, 8, 2)
    search_kernel<<<grid, STHREADS>>>(y_true, y_pred, out);
}

// round 12
// speedup vs baseline: 3.4563x; 1.4043x over previous
#include <cuda_runtime.h>

// Problem constants (fixed by the reference: B=8, N=4096, D=2)
#define BQ       8
#define NPTS     4096
#define NSETS    16                  // 8 batches x {y_true, y_pred}
#define NBINS    512
#define XMAX     5.0f
#define BINW     (2.0f * XMAX / NBINS)
#define BSCALE   (NBINS / (2.0f * XMAX))
#define PTHREADS 512
#define STHREADS 512
#define NB_B     128                 // search blocks: 8 tiles x 8 batches x 2 dirs
#define MINSPAN  96                  // initial candidate window (>= 3 warp rounds)
#define F_INF    0x7f800000u

// Scratch (device globals — allocation-free per harness rules)
__device__ float2 g_pts[NSETS][NPTS];            // bin-ordered points
__device__ int    g_binStart[NSETS][NBINS + 1];  // bin b occupies [start[b], start[b+1])
__device__ float  g_partials[NB_B];
__device__ int    g_counter = 0;                 // reset by last search block

__device__ __forceinline__ int binOf(float x) {
    int b = (int)((x + XMAX) * BSCALE);
    return min(max(b, 0), NBINS - 1);
}
__device__ __forceinline__ float binEdge(int b) {   // left edge of bin b
    return -XMAX + (float)b * BINW;
}

// ─────────────── Kernel A: counting sort by x-bin (bin sets deterministic) ───
__global__ __launch_bounds__(PTHREADS, 1)
void prep_kernel(const float* __restrict__ yt, const float* __restrict__ yp) {
    __shared__ int hist[NBINS];       // histogram, then scatter cursors
    __shared__ int scn[NBINS];        // inclusive-scan workspace
    __shared__ int start[NBINS + 1];  // exclusive prefix

    const int tid = threadIdx.x;
    const int s   = blockIdx.x;
    const float2* src = reinterpret_cast<const float2*>(((s & 1) ? yp : yt))
                      + (size_t)(s >> 1) * NPTS;

    if (tid < NBINS) hist[tid] = 0;
    __syncthreads();
    for (int i = tid; i < NPTS; i += PTHREADS)
        atomicAdd(&hist[binOf(src[i].x)], 1);
    __syncthreads();

    // Inclusive scan over 512 bins (Hillis–Steele).
    if (tid < NBINS) scn[tid] = hist[tid];
    __syncthreads();
    for (int off = 1; off < NBINS; off <<= 1) {
        int v = 0;
        if (tid < NBINS && tid >= off) v = scn[tid - off];
        __syncthreads();
        if (tid < NBINS) scn[tid] += v;
        __syncthreads();
    }
    if (tid == 0) start[0] = 0;
    if (tid < NBINS) start[tid + 1] = scn[tid];
    if (tid < NBINS) hist[tid] = 0;   // reset cursors
    __syncthreads();

    // Scatter. Within-bin ORDER is atomic-dependent, but the per-bin SET and
    // all bin counts are deterministic; search only takes set-wise mins over
    // whole bins, so the final output is bit-deterministic.
    for (int i = tid; i < NPTS; i += PTHREADS) {
        const float2 p = src[i];
        const int bb = binOf(p.x);
        const int pos = start[bb] + atomicAdd(&hist[bb], 1);
        g_pts[s][pos] = p;
    }
    for (int i = tid; i <= NBINS; i += PTHREADS)
        g_binStart[s][i] = start[i];
}

// ─────────── Kernel B: warp-cooperative exact NN over shared bins ────────────
// Grid (8 tiles, 8 batches, 2 dirs). Each warp processes 32 queries one at a
// time; all 32 lanes scan one query's contiguous candidate span in parallel.
__global__ __launch_bounds__(STHREADS, 1)
void search_kernel(const float* __restrict__ yt, const float* __restrict__ yp,
                   float* __restrict__ out) {
    __shared__ float2 shPts[NPTS];        // 32 KB: bin-ordered reference set
    __shared__ int    shStart[NBINS + 1]; //  2 KB
    __shared__ float  red[STHREADS];      //  2 KB
    __shared__ bool   isLast;

    const int tid  = threadIdx.x;
    const int lane = tid & 31;
    const int dir  = blockIdx.z;
    const int b    = blockIdx.y;
    const int sr   = (b << 1) | (1 - dir);   // reference set id
    const float2* qsrc = reinterpret_cast<const float2*>(dir == 0 ? yt : yp)
                       + (size_t)b * NPTS;

    // Stage reference set + bin index (coalesced).
    for (int i = tid; i < NPTS; i += STHREADS) shPts[i] = g_pts[sr][i];
    for (int i = tid; i <= NBINS; i += STHREADS) shStart[i] = g_binStart[sr][i];
    __syncthreads();

    // Thread tid owns query (original index) p0 + tid; warp processes its 32
    // queries one at a time (lane i's query at iteration i).
    const int qbase = blockIdx.x * STHREADS + (tid >> 5) * 32;
    const float2 myq = qsrc[qbase + lane];
    float myBest = 0.0f;

    for (int i = 0; i < 32; i++) {
        const float qx = __shfl_sync(0xffffffffu, myq.x, i);
        const float qy = __shfl_sync(0xffffffffu, myq.y, i);
        const int qb = binOf(qx);
        int lo = qb, hi = qb;
        int s0 = shStart[qb], s1 = shStart[qb + 1];

        // Grow window (whole bins, nearer side first) to >= MINSPAN candidates.
        while (s1 - s0 < MINSPAN && (lo > 0 || hi < NBINS - 1)) {
            const float lgap = (lo > 0)         ? (qx - binEdge(lo))     : __int_as_float(0x7f800000);
            const float rgap = (hi < NBINS - 1) ? (binEdge(hi + 1) - qx) : __int_as_float(0x7f800000);
            if (lgap <= rgap) { lo--; s0 = shStart[lo]; }
            else              { hi++; s1 = shStart[hi + 1]; }
        }

        // Lane-parallel scan of the contiguous span (d2 >= 0, so uint bits
        // order-match floats; min over a set is exact => order-invariant).
        unsigned ub = F_INF;
        for (int j = s0 + lane; j < s1; j += 32) {
            const float2 r = shPts[j];
            const float dx = r.x - qx, dy = r.y - qy;
            ub = min(ub, __float_as_uint(fmaf(dx, dx, dy * dy)));
        }
        unsigned wbest = __reduce_min_sync(0xffffffffu, ub);

        // Certificate expansion: every unscanned point has |dx| >= gap.
        for (;;) {
            const float lgap = (lo > 0)         ? (qx - binEdge(lo))     : __int_as_float(0x7f800000);
            const float rgap = (hi < NBINS - 1) ? (binEdge(hi + 1) - qx) : __int_as_float(0x7f800000);
            const float gap  = fminf(lgap, rgap);
            if (gap * gap >= __uint_as_float(wbest)) break;
            int nb;
            if (lgap <= rgap) { lo--; nb = lo; } else { hi++; nb = hi; }
            const int t0 = shStart[nb], t1 = shStart[nb + 1];
            unsigned u2 = wbest;
            for (int j = t0 + lane; j < t1; j += 32) {
                const float2 r = shPts[j];
                const float dx = r.x - qx, dy = r.y - qy;
                u2 = min(u2, __float_as_uint(fmaf(dx, dx, dy * dy)));
            }
            wbest = __reduce_min_sync(0xffffffffu, u2);
        }
        if (lane == i) myBest = __uint_as_float(wbest);
    }

    // Chamfer contribution (d2 >= 0 by construction, matches reference clamp).
    float local = myBest * (1.0f / BQ);

    // Fused EMD (dir-0 blocks own exactly the y_true indices they query):
    // cumsum over D=2 -> (t0-p0)^2 + (t0+t1-p0-p1)^2, index-aligned pairs.
    if (dir == 0) {
        const int p = qbase + lane;
        const float2 tv = reinterpret_cast<const float2*>(yt)[(size_t)b * NPTS + p];
        const float2 pv = reinterpret_cast<const float2*>(yp)[(size_t)b * NPTS + p];
        const float d0 = tv.x - pv.x;
        const float d1 = (tv.x + tv.y) - (pv.x + pv.y);
        local += (d0 * d0 + d1 * d1) * (1.0f / ((float)BQ * NPTS * 2));
    }

    // Deterministic block tree reduction (thread <-> original query index).
    red[tid] = local;
    __syncthreads();
    for (int w = STHREADS / 2; w > 0; w >>= 1) {
        if (tid < w) red[tid] += red[tid + w];
        __syncthreads();
    }
    const int bid = (blockIdx.z * gridDim.y + blockIdx.y) * gridDim.x + blockIdx.x;
    if (tid == 0) {
        g_partials[bid] = red[0];
        __threadfence();
        const int c = atomicAdd(&g_counter, 1);
        isLast = (c == NB_B - 1);
    }
    __syncthreads();

    // Last block: deterministic fixed-order sum of the 128 partials.
    if (isLast) {
        float v = 0.0f;
        if (tid < NB_B) {
            __threadfence();
            v = *((volatile float*)&g_partials[tid]);
        }
        red[tid] = v;
        __syncthreads();
        for (int w = STHREADS / 2; w > 0; w >>= 1) {
            if (tid < w) red[tid] += red[tid + w];
            __syncthreads();
        }
        if (tid == 0) {
            out[0] = red[0];
            g_counter = 0;   // reset for next graph replay
        }
    }
}

extern "C" void kernel_launch(void* const* d_in, const int* in_sizes, int n_in,
                              void* d_out, int out_size) {
    const float* y_true = (const float*)d_in[0];
    const float* y_pred = (const float*)d_in[1];
    float* out = (float*)d_out;

    prep_kernel<<<NSETS, PTHREADS>>>(y_true, y_pred);
    dim3 grid(NPTS / STHREADS, BQ, 2);   // (8, 8, 2)
    search_kernel<<<grid, STHREADS>>>(y_true, y_pred, out);
}